// round 3
// baseline (speedup 1.0000x reference)
#include <cuda_runtime.h>
#include <cuda_bf16.h>
#include <cstdint>
#include <math.h>

#define Bq 8
#define Nq 20000
#define Dq 1024
#define NT (Bq*Nq)      // 160000 tiles
#define BM 64           // tiles per block (k1)
#define KB 16           // k-chunk size
#define KBS 20          // padded row stride in floats (16B-aligned rows, conflict-free)
#define NCH (Dq/KB)     // 64 chunks
#define KSEL 10

static __device__ float g_scores[NT];
static __device__ float g_outv[NT*32];

__device__ __forceinline__ unsigned long long ffma2(unsigned long long a, unsigned long long b, unsigned long long c){
    unsigned long long d;
    asm("fma.rn.f32x2 %0, %1, %2, %3;" : "=l"(d) : "l"(a), "l"(b), "l"(c));
    return d;
}
__device__ __forceinline__ void cp16(float* dst, const float* src){
    unsigned s = (unsigned)__cvta_generic_to_shared(dst);
    asm volatile("cp.async.cg.shared.global [%0], [%1], 16;" :: "r"(s), "l"(src) : "memory");
}

// ---------------- Kernel 1: per-tile MLP (layer1 GEMM + layers 2-3 + score head) ----
// One warp per block, 64 tiles/block, f32x2-packed accumulators, TT=8 x TC=8
// register blocking, cp.async double buffering.
__global__ __launch_bounds__(32, 8) void k1(
    const float* __restrict__ x,  const float* __restrict__ W1, const float* __restrict__ b1,
    const float* __restrict__ W2, const float* __restrict__ b2,
    const float* __restrict__ W3, const float* __restrict__ b3,
    const float* __restrict__ Wsc, const float* __restrict__ bsc)
{
    __shared__ __align__(16) float xs[2][BM*KBS];
    __shared__ __align__(16) float ws[2][32*KBS];
    __shared__ float h1s[BM*33];
    __shared__ float sW2[256], sW3[256], sB2[8], sB3[32], sWsc[32], sB1[32];
    __shared__ float sBsc;

    const int tid = threadIdx.x;
    const int t0  = blockIdx.x * BM;
    const int tg  = tid & 7;    // tile group 0..7
    const int cg  = tid >> 3;   // channel group 0..3

    for (int i = tid; i < 256; i += 32){ sW2[i] = W2[i]; sW3[i] = W3[i]; }
    sB3[tid] = b3[tid]; sWsc[tid] = Wsc[tid]; sB1[tid] = b1[tid];
    if (tid < 8) sB2[tid] = b2[tid];
    if (tid == 0) sBsc = bsc[0];

    unsigned long long acc[8][8];
#pragma unroll
    for (int a=0;a<8;a++)
#pragma unroll
        for (int c=0;c<8;c++) acc[a][c] = 0ull;

    // prologue: stage chunk 0 into buffer 0
#pragma unroll
    for (int j=0;j<8;j++){
        int i = tid + 32*j; int row = i>>2, q = i&3;
        cp16(&xs[0][row*KBS + q*4], x + (size_t)(t0+row)*Dq + q*4);
    }
#pragma unroll
    for (int j=0;j<4;j++){
        int i = tid + 32*j; int row = i>>2, q = i&3;
        cp16(&ws[0][row*KBS + q*4], W1 + (size_t)row*Dq + q*4);
    }
    asm volatile("cp.async.commit_group;" ::: "memory");

    for (int kc=0; kc<NCH; kc++){
        const int bb = kc & 1;
        if (kc+1 < NCH){
            const int k0 = (kc+1)*KB, nb = bb^1;
#pragma unroll
            for (int j=0;j<8;j++){
                int i = tid + 32*j; int row = i>>2, q = i&3;
                cp16(&xs[nb][row*KBS + q*4], x + (size_t)(t0+row)*Dq + k0 + q*4);
            }
#pragma unroll
            for (int j=0;j<4;j++){
                int i = tid + 32*j; int row = i>>2, q = i&3;
                cp16(&ws[nb][row*KBS + q*4], W1 + (size_t)row*Dq + k0 + q*4);
            }
            asm volatile("cp.async.commit_group;" ::: "memory");
            asm volatile("cp.async.wait_group 1;"  ::: "memory");
        } else {
            asm volatile("cp.async.wait_group 0;"  ::: "memory");
        }
        __syncwarp();

        const ulonglong2* xp = reinterpret_cast<const ulonglong2*>(xs[bb]);
        const ulonglong2* wp = reinterpret_cast<const ulonglong2*>(ws[bb]);
#pragma unroll
        for (int q=0;q<KB/4;q++){
            ulonglong2 xv[8], wv[8];
#pragma unroll
            for (int tt=0;tt<8;tt++) xv[tt] = xp[(tg + 8*tt)*5 + q];   // KBS/4 = 5
#pragma unroll
            for (int cc=0;cc<8;cc++) wv[cc] = wp[(cg + 4*cc)*5 + q];
#pragma unroll
            for (int tt=0;tt<8;tt++)
#pragma unroll
                for (int cc=0;cc<8;cc++){
                    acc[tt][cc] = ffma2(xv[tt].x, wv[cc].x, acc[tt][cc]);
                    acc[tt][cc] = ffma2(xv[tt].y, wv[cc].y, acc[tt][cc]);
                }
        }
        __syncwarp();
    }

    // reduce f32x2 pairs, add bias, relu -> h1 in smem
#pragma unroll
    for (int tt=0;tt<8;tt++)
#pragma unroll
        for (int cc=0;cc<8;cc++){
            int m = tg + 8*tt, c = cg + 4*cc;
            unsigned long long a = acc[tt][cc];
            float lo = __uint_as_float((unsigned)(a & 0xFFFFFFFFull));
            float hi = __uint_as_float((unsigned)(a >> 32));
            float v = lo + hi + sB1[c];
            h1s[m*33 + c] = v > 0.f ? v : 0.f;
        }
    __syncwarp();

    // layers 2-3 + score head, 2 tiles per lane
#pragma unroll
    for (int r=0;r<2;r++){
        const int m = tid + 32*r;
        const size_t t = (size_t)t0 + m;
        float hv[32];
#pragma unroll
        for (int h=0;h<32;h++) hv[h] = h1s[m*33 + h];
        float h2[8];
#pragma unroll
        for (int g=0;g<8;g++){
            float s = sB2[g];
#pragma unroll
            for (int h=0;h<32;h++) s = fmaf(sW2[g*32+h], hv[h], s);
            h2[g] = s > 0.f ? s : 0.f;
        }
        float sc = sBsc;
#pragma unroll
        for (int h4=0;h4<8;h4++){
            float4 o4;
            float* op = &o4.x;
#pragma unroll
            for (int k=0;k<4;k++){
                const int h = h4*4 + k;
                float s = sB3[h];
#pragma unroll
                for (int g=0;g<8;g++) s = fmaf(sW3[h*8+g], h2[g], s);
                s = s > 0.f ? s : 0.f;
                op[k] = s;
                sc = fmaf(sWsc[h], s, sc);
            }
            *reinterpret_cast<float4*>(&g_outv[t*32 + h4*4]) = o4;
        }
        g_scores[t] = sc > 0.f ? sc : 0.f;
    }
}

// ---------------- Kernel 2: stable top/bottom-k select + classifier ----------------
// Key = (score_bits << 32) | index replicates jnp.argsort's stable (score, index)
// ordering exactly (scores are >= 0 after relu, so float bits are monotonic).
__global__ __launch_bounds__(256) void k2(
    const float* __restrict__ Wc1, const float* __restrict__ bc1,
    const float* __restrict__ Wc2, const float* __restrict__ bc2,
    const float* __restrict__ Wc3, const float* __restrict__ bc3,
    float* __restrict__ outp)
{
    const int b = blockIdx.x, tid = threadIdx.x;   // 256 threads
    __shared__ unsigned long long botC[2560], topC[2560], red[256], selkey[20];
    __shared__ float feat[692], z1[32], z2[32];

    unsigned long long bot[KSEL], top[KSEL];
#pragma unroll
    for (int j=0;j<KSEL;j++){ bot[j] = ~0ull; top[j] = 0ull; }

    for (int n = tid; n < Nq; n += 256){
        float s = g_scores[(size_t)b*Nq + n];
        unsigned long long key = ((unsigned long long)__float_as_uint(s) << 32) | (unsigned)n;
        if (key < bot[KSEL-1]){
            int p = KSEL-1;
            while (p > 0 && bot[p-1] > key){ bot[p] = bot[p-1]; p--; }
            bot[p] = key;
        }
        if (key > top[0]){
            int p = 0;
            while (p < KSEL-1 && top[p+1] < key){ top[p] = top[p+1]; p++; }
            top[p] = key;
        }
    }
#pragma unroll
    for (int j=0;j<KSEL;j++){ botC[tid*KSEL+j] = bot[j]; topC[tid*KSEL+j] = top[j]; }
    __syncthreads();

    // bottom-10 ascending -> selkey[0..9]
    unsigned long long prev = 0ull;
    for (int i=0;i<KSEL;i++){
        unsigned long long best = ~0ull;
        for (int j=tid;j<2560;j+=256){
            unsigned long long v = botC[j];
            if ((i==0 || v>prev) && v<best) best = v;
        }
        red[tid] = best; __syncthreads();
        for (int s=128;s>0;s>>=1){ if (tid<s){ if (red[tid+s]<red[tid]) red[tid]=red[tid+s]; } __syncthreads(); }
        if (tid==0) selkey[i] = red[0];
        __syncthreads();
        prev = selkey[i];
    }
    // top-10: extract maxima descending, store ascending at 19..10
    unsigned long long prevT = 0ull;
    for (int i=0;i<KSEL;i++){
        unsigned long long best = 0ull;
        for (int j=tid;j<2560;j+=256){
            unsigned long long v = topC[j];
            if ((i==0 || v<prevT) && v>best) best = v;
        }
        red[tid] = best; __syncthreads();
        for (int s=128;s>0;s>>=1){ if (tid<s){ if (red[tid+s]>red[tid]) red[tid]=red[tid+s]; } __syncthreads(); }
        if (tid==0) selkey[19-i] = red[0];
        __syncthreads();
        prevT = selkey[19-i];
    }
    __syncthreads();

    // features: feat = [g_sc(0..19) | avg(20..51) | g_flat(52..691): 52 + h*20 + j]
    for (int i = tid; i < 640; i += 256){
        int j = i >> 5, h = i & 31;
        int n = (int)(selkey[j] & 0xFFFFFFFFull);
        feat[52 + h*20 + j] = g_outv[((size_t)b*Nq + n)*32 + h];
    }
    if (tid < 20) feat[tid] = __uint_as_float((unsigned)(selkey[tid] >> 32));
    __syncthreads();
    if (tid < 32){
        float s = 0.f;
#pragma unroll
        for (int j=0;j<20;j++) s += feat[52 + tid*20 + j];
        feat[20 + tid] = s * (1.f/20.f);
    }
    __syncthreads();

    // classifier: 692 -> 32 -> 32 -> 1
    if (tid < 32){
        float s = bc1[tid];
        const float* wr = Wc1 + (size_t)tid*692;
        for (int i=0;i<692;i++) s = fmaf(wr[i], feat[i], s);
        z1[tid] = s > 0.f ? s : 0.f;
    }
    __syncthreads();
    if (tid < 32){
        float s = bc2[tid];
#pragma unroll
        for (int i=0;i<32;i++) s = fmaf(Wc2[tid*32+i], z1[i], s);
        z2[tid] = s > 0.f ? s : 0.f;
    }
    __syncthreads();
    if (tid == 0){
        float s = bc3[0];
#pragma unroll
        for (int i=0;i<32;i++) s = fmaf(Wc3[i], z2[i], s);
        outp[b] = 1.f / (1.f + expf(-s));
    }
}

extern "C" void kernel_launch(void* const* d_in, const int* in_sizes, int n_in,
                              void* d_out, int out_size) {
    const float* x   = (const float*)d_in[0];
    const float* W1  = (const float*)d_in[1];
    const float* b1  = (const float*)d_in[2];
    const float* W2  = (const float*)d_in[3];
    const float* b2  = (const float*)d_in[4];
    const float* W3  = (const float*)d_in[5];
    const float* b3  = (const float*)d_in[6];
    const float* Wsc = (const float*)d_in[7];
    const float* bsc = (const float*)d_in[8];
    const float* Wc1 = (const float*)d_in[9];
    const float* bc1 = (const float*)d_in[10];
    const float* Wc2 = (const float*)d_in[11];
    const float* bc2 = (const float*)d_in[12];
    const float* Wc3 = (const float*)d_in[13];
    const float* bc3 = (const float*)d_in[14];
    float* outp = (float*)d_out;

    k1<<<NT/BM, 32>>>(x, W1, b1, W2, b2, W3, b3, Wsc, bsc);
    k2<<<Bq, 256>>>(Wc1, bc1, Wc2, bc2, Wc3, bc3, outp);
}

// round 5
// speedup vs baseline: 1.7840x; 1.7840x over previous
#include <cuda_runtime.h>
#include <cuda_bf16.h>
#include <cstdint>
#include <math.h>

#define Bq 8
#define Nq 20000
#define Dq 1024
#define NT (Bq*Nq)      // 160000 tiles
#define KSEL 10
#define MT 128          // tiles per CTA (k1)
#define NCHK 16         // K chunks of 64

static __device__ float g_scores[NT];
static __device__ float g_outv[NT*32];

#define SWZ(o) ((o) ^ (((o) >> 3) & 0x70))

// float smem offsets (weights region)
#define F_W2  0
#define F_W3  256
#define F_B1  512
#define F_B2  544
#define F_B3  552
#define F_WSC 584
#define F_BSC 616
// byte offsets (stage region)
#define O_STAGE 4096
#define STG_SZ  40960
#define S_AH 0
#define S_AL 16384
#define S_BH 32768
#define S_BL 36864
#define SMEM_K1 (O_STAGE + 2*STG_SZ)   // 86016 B

__device__ __forceinline__ uint32_t s2u(const void* p){
    uint32_t a;
    asm("{ .reg .u64 t; cvta.to.shared.u64 t, %1; cvt.u32.u64 %0, t; }" : "=r"(a) : "l"(p));
    return a;
}
// pack {bf16(x1):bf16(x0)} (x0 in low half)
__device__ __forceinline__ uint32_t bf2pack(float x0, float x1){
    uint32_t r; asm("cvt.rn.bf16x2.f32 %0, %1, %2;" : "=r"(r) : "f"(x1), "f"(x0)); return r;
}
__device__ __forceinline__ void ldsm4(uint32_t a, uint32_t r[4]){
    asm volatile("ldmatrix.sync.aligned.m8n8.x4.shared.b16 {%0,%1,%2,%3}, [%4];"
        : "=r"(r[0]), "=r"(r[1]), "=r"(r[2]), "=r"(r[3]) : "r"(a));
}
__device__ __forceinline__ void mma16816(float c[4], const uint32_t a[4], uint32_t b0, uint32_t b1){
    asm volatile("mma.sync.aligned.m16n8k16.row.col.f32.bf16.bf16.f32 "
        "{%0,%1,%2,%3}, {%4,%5,%6,%7}, {%8,%9}, {%0,%1,%2,%3};"
        : "+f"(c[0]), "+f"(c[1]), "+f"(c[2]), "+f"(c[3])
        : "r"(a[0]), "r"(a[1]), "r"(a[2]), "r"(a[3]), "r"(b0), "r"(b1));
}

// ======= Kernel 1: bf16-split HMMA GEMM (M=128,N=32,K=1024) + fused MLP epilogue ===
__global__ __launch_bounds__(256, 2)
void k1(const float* __restrict__ x,  const float* __restrict__ W1, const float* __restrict__ b1,
        const float* __restrict__ W2, const float* __restrict__ b2,
        const float* __restrict__ W3, const float* __restrict__ b3,
        const float* __restrict__ Wsc, const float* __restrict__ bsc)
{
    extern __shared__ char smem[];
    float* sf = (float*)smem;
    const uint32_t sb = s2u(smem);
    const int tid = threadIdx.x;
    const int wid = tid >> 5;
    const int lid = tid & 31;
    const int t0  = blockIdx.x * MT;

    // small weights into smem
    for (int i = tid; i < 256; i += 256){ sf[F_W2 + i] = W2[i]; sf[F_W3 + i] = W3[i]; }
    if (tid < 32){ sf[F_B1 + tid] = b1[tid]; sf[F_B3 + tid] = b3[tid]; sf[F_WSC + tid] = Wsc[tid]; }
    if (tid < 8) sf[F_B2 + tid] = b2[tid];
    if (tid == 0) sf[F_BSC] = bsc[0];

    float4 ra[8], rb[2];

    // ---- load chunk c into registers
    auto LD = [&](int c){
        const int k0 = c * 64;
#pragma unroll
        for (int j = 0; j < 8; j++){
            int f = tid + 256*j; int row = f >> 4, qc = f & 15;
            ra[j] = __ldg((const float4*)(x + (size_t)(t0 + row) * Dq + k0) + qc);
        }
#pragma unroll
        for (int j = 0; j < 2; j++){
            int f = tid + 256*j; int row = f >> 4, qc = f & 15;
            rb[j] = __ldg((const float4*)(W1 + (size_t)row * Dq + k0) + qc);
        }
    };
    // ---- split + store registers into stage buffer
    auto ST = [&](int buf){
        const uint32_t stg = O_STAGE + buf * STG_SZ;
#pragma unroll
        for (int j = 0; j < 8; j++){
            int f = tid + 256*j; int row = f >> 4, qc = f & 15;
            float4 v = ra[j];
            uint32_t h0 = bf2pack(v.x, v.y), h1 = bf2pack(v.z, v.w);
            float hx = __uint_as_float(h0 << 16), hy = __uint_as_float(h0 & 0xffff0000u);
            float hz = __uint_as_float(h1 << 16), hw = __uint_as_float(h1 & 0xffff0000u);
            uint32_t l0 = bf2pack(v.x - hx, v.y - hy), l1 = bf2pack(v.z - hz, v.w - hw);
            uint32_t bo = SWZ((uint32_t)(row * 128 + qc * 8));
            *(uint2*)(smem + stg + S_AH + bo) = make_uint2(h0, h1);
            *(uint2*)(smem + stg + S_AL + bo) = make_uint2(l0, l1);
        }
#pragma unroll
        for (int j = 0; j < 2; j++){
            int f = tid + 256*j; int row = f >> 4, qc = f & 15;
            float4 v = rb[j];
            uint32_t h0 = bf2pack(v.x, v.y), h1 = bf2pack(v.z, v.w);
            float hx = __uint_as_float(h0 << 16), hy = __uint_as_float(h0 & 0xffff0000u);
            float hz = __uint_as_float(h1 << 16), hw = __uint_as_float(h1 & 0xffff0000u);
            uint32_t l0 = bf2pack(v.x - hx, v.y - hy), l1 = bf2pack(v.z - hz, v.w - hw);
            uint32_t bo = SWZ((uint32_t)(row * 128 + qc * 8));
            *(uint2*)(smem + stg + S_BH + bo) = make_uint2(h0, h1);
            *(uint2*)(smem + stg + S_BL + bo) = make_uint2(l0, l1);
        }
    };

    // prologue
    LD(0);
    ST(0);
    __syncthreads();

    float acc[4][4];
#pragma unroll
    for (int i = 0; i < 4; i++)
#pragma unroll
        for (int j = 0; j < 4; j++) acc[i][j] = 0.f;

    const int arow = wid * 16 + (lid & 15);
    const int bn   = (lid & 7) + ((lid >> 4) * 8);

    for (int c = 0; c < NCHK; c++){
        if (c + 1 < NCHK) LD(c + 1);
        const uint32_t stg = O_STAGE + (c & 1) * STG_SZ;
#pragma unroll
        for (int k = 0; k < 4; k++){
            uint32_t ah[4], al[4];
            uint32_t ab = SWZ((uint32_t)(arow * 128 + k * 32 + ((lid >> 4) * 16)));
            ldsm4(sb + stg + S_AH + ab, ah);
            ldsm4(sb + stg + S_AL + ab, al);
            const uint32_t kb = (uint32_t)(k * 32 + ((lid >> 3) & 1) * 16);
#pragma unroll
            for (int nb2 = 0; nb2 < 2; nb2++){
                uint32_t bh[4], bl[4];
                uint32_t bb = SWZ((uint32_t)((nb2 * 16 + bn) * 128) + kb);
                ldsm4(sb + stg + S_BH + bb, bh);
                ldsm4(sb + stg + S_BL + bb, bl);
                mma16816(acc[nb2*2],   ah, bh[0], bh[1]);
                mma16816(acc[nb2*2+1], ah, bh[2], bh[3]);
                mma16816(acc[nb2*2],   ah, bl[0], bl[1]);
                mma16816(acc[nb2*2+1], ah, bl[2], bl[3]);
                mma16816(acc[nb2*2],   al, bh[0], bh[1]);
                mma16816(acc[nb2*2+1], al, bh[2], bh[3]);
            }
        }
        if (c + 1 < NCHK){
            ST((c + 1) & 1);
            __syncthreads();
        }
    }

    // epilogue: write h1 (pre-bias) into smem (reuses buf0 region; safe: buf0 last
    // read at chunk 14, barrier at end of iter 14 covers it; chunk 15 reads buf1)
    float* h1s = (float*)(smem + O_STAGE);
    {
        const int gid = lid >> 2, qd = lid & 3;
        const int r0 = wid * 16 + gid, r1 = r0 + 8;
#pragma unroll
        for (int nsub = 0; nsub < 4; nsub++){
            h1s[r0*33 + nsub*8 + qd*2 + 0] = acc[nsub][0];
            h1s[r0*33 + nsub*8 + qd*2 + 1] = acc[nsub][1];
            h1s[r1*33 + nsub*8 + qd*2 + 0] = acc[nsub][2];
            h1s[r1*33 + nsub*8 + qd*2 + 1] = acc[nsub][3];
        }
    }
    __syncthreads();

    if (tid < MT){
        const int m = tid;
        const size_t t = (size_t)t0 + m;
        float hv[32];
#pragma unroll
        for (int h = 0; h < 32; h++){
            float v = h1s[m*33 + h] + sf[F_B1 + h];
            hv[h] = v > 0.f ? v : 0.f;
        }
        float h2[8];
#pragma unroll
        for (int g = 0; g < 8; g++){
            float s = sf[F_B2 + g];
#pragma unroll
            for (int h = 0; h < 32; h++) s = fmaf(sf[F_W2 + g*32 + h], hv[h], s);
            h2[g] = s > 0.f ? s : 0.f;
        }
        float sc = sf[F_BSC];
#pragma unroll
        for (int h4 = 0; h4 < 8; h4++){
            float4 o4; float* op = &o4.x;
#pragma unroll
            for (int kk = 0; kk < 4; kk++){
                const int h = h4*4 + kk;
                float s = sf[F_B3 + h];
#pragma unroll
                for (int g = 0; g < 8; g++) s = fmaf(sf[F_W3 + h*8 + g], h2[g], s);
                s = s > 0.f ? s : 0.f;
                op[kk] = s;
                sc = fmaf(sf[F_WSC + h], s, sc);
            }
            *(float4*)(&g_outv[t*32 + h4*4]) = o4;
        }
        g_scores[t] = sc > 0.f ? sc : 0.f;
    }
}

// ======= Kernel 2: stable top/bottom-k select + classifier ========================
// Key = (score_bits << 32) | index replicates jnp.argsort stable (score, index) order.
__global__ __launch_bounds__(256) void k2(
    const float* __restrict__ Wc1, const float* __restrict__ bc1,
    const float* __restrict__ Wc2, const float* __restrict__ bc2,
    const float* __restrict__ Wc3, const float* __restrict__ bc3,
    float* __restrict__ outp)
{
    const int b = blockIdx.x, tid = threadIdx.x;
    __shared__ unsigned long long botC[2560], topC[2560], red[256], selkey[20];
    __shared__ float feat[692], z1[32], z2[32];

    unsigned long long bot[KSEL], top[KSEL];
#pragma unroll
    for (int j = 0; j < KSEL; j++){ bot[j] = ~0ull; top[j] = 0ull; }

    const float4* sp = (const float4*)(g_scores + (size_t)b * Nq);
    for (int v = tid; v < Nq/4; v += 256){
        float4 s4 = sp[v];
        float ss[4] = {s4.x, s4.y, s4.z, s4.w};
#pragma unroll
        for (int e = 0; e < 4; e++){
            unsigned long long key = ((unsigned long long)__float_as_uint(ss[e]) << 32) | (unsigned)(v*4 + e);
            if (key < bot[KSEL-1]){
                int p = KSEL-1;
                while (p > 0 && bot[p-1] > key){ bot[p] = bot[p-1]; p--; }
                bot[p] = key;
            }
            if (key > top[0]){
                int p = 0;
                while (p < KSEL-1 && top[p+1] < key){ top[p] = top[p+1]; p++; }
                top[p] = key;
            }
        }
    }
#pragma unroll
    for (int j = 0; j < KSEL; j++){ botC[tid*KSEL+j] = bot[j]; topC[tid*KSEL+j] = top[j]; }
    __syncthreads();

    unsigned long long prev = 0ull;
    for (int i = 0; i < KSEL; i++){
        unsigned long long best = ~0ull;
        for (int j = tid; j < 2560; j += 256){
            unsigned long long v = botC[j];
            if ((i == 0 || v > prev) && v < best) best = v;
        }
        red[tid] = best; __syncthreads();
        for (int s = 128; s > 0; s >>= 1){ if (tid < s){ if (red[tid+s] < red[tid]) red[tid] = red[tid+s]; } __syncthreads(); }
        if (tid == 0) selkey[i] = red[0];
        __syncthreads();
        prev = selkey[i];
    }
    unsigned long long prevT = 0ull;
    for (int i = 0; i < KSEL; i++){
        unsigned long long best = 0ull;
        for (int j = tid; j < 2560; j += 256){
            unsigned long long v = topC[j];
            if ((i == 0 || v < prevT) && v > best) best = v;
        }
        red[tid] = best; __syncthreads();
        for (int s = 128; s > 0; s >>= 1){ if (tid < s){ if (red[tid+s] > red[tid]) red[tid] = red[tid+s]; } __syncthreads(); }
        if (tid == 0) selkey[19-i] = red[0];
        __syncthreads();
        prevT = selkey[19-i];
    }
    __syncthreads();

    // features: [g_sc(0..19) | avg(20..51) | g_flat(52..691): 52 + h*20 + j]
    for (int i = tid; i < 640; i += 256){
        int j = i >> 5, h = i & 31;
        int n = (int)(selkey[j] & 0xFFFFFFFFull);
        feat[52 + h*20 + j] = g_outv[((size_t)b*Nq + n)*32 + h];
    }
    if (tid < 20) feat[tid] = __uint_as_float((unsigned)(selkey[tid] >> 32));
    __syncthreads();
    if (tid < 32){
        float s = 0.f;
#pragma unroll
        for (int j = 0; j < 20; j++) s += feat[52 + tid*20 + j];
        feat[20 + tid] = s * (1.f/20.f);
    }
    __syncthreads();

    // classifier layer 1: 8 threads per output + shfl reduce
    {
        int o = tid >> 3, p = tid & 7;
        const float* wr = Wc1 + (size_t)o * 692;
        float s = 0.f;
        for (int i = p; i < 692; i += 8) s = fmaf(wr[i], feat[i], s);
        s += __shfl_xor_sync(0xffffffffu, s, 1);
        s += __shfl_xor_sync(0xffffffffu, s, 2);
        s += __shfl_xor_sync(0xffffffffu, s, 4);
        if (p == 0){ s += bc1[o]; z1[o] = s > 0.f ? s : 0.f; }
    }
    __syncthreads();
    if (tid < 32){
        float s = bc2[tid];
#pragma unroll
        for (int i = 0; i < 32; i++) s = fmaf(Wc2[tid*32+i], z1[i], s);
        z2[tid] = s > 0.f ? s : 0.f;
    }
    __syncthreads();
    if (tid == 0){
        float s = bc3[0];
#pragma unroll
        for (int i = 0; i < 32; i++) s = fmaf(Wc3[i], z2[i], s);
        outp[b] = 1.f / (1.f + expf(-s));
    }
}

extern "C" void kernel_launch(void* const* d_in, const int* in_sizes, int n_in,
                              void* d_out, int out_size) {
    const float* x   = (const float*)d_in[0];
    const float* W1  = (const float*)d_in[1];
    const float* b1  = (const float*)d_in[2];
    const float* W2  = (const float*)d_in[3];
    const float* b2  = (const float*)d_in[4];
    const float* W3  = (const float*)d_in[5];
    const float* b3  = (const float*)d_in[6];
    const float* Wsc = (const float*)d_in[7];
    const float* bsc = (const float*)d_in[8];
    const float* Wc1 = (const float*)d_in[9];
    const float* bc1 = (const float*)d_in[10];
    const float* Wc2 = (const float*)d_in[11];
    const float* bc2 = (const float*)d_in[12];
    const float* Wc3 = (const float*)d_in[13];
    const float* bc3 = (const float*)d_in[14];
    float* outp = (float*)d_out;

    cudaFuncSetAttribute(k1, cudaFuncAttributeMaxDynamicSharedMemorySize, SMEM_K1);
    k1<<<NT/MT, 256, SMEM_K1>>>(x, W1, b1, W2, b2, W3, b3, Wsc, bsc);
    k2<<<Bq, 256>>>(Wc1, bc1, Wc2, bc2, Wc3, bc3, outp);
}

// round 6
// speedup vs baseline: 2.1274x; 1.1925x over previous
#include <cuda_runtime.h>
#include <cuda_bf16.h>
#include <cstdint>
#include <math.h>

#define Bq 8
#define Nq 20000
#define Dq 1024
#define NT (Bq*Nq)      // 160000 tiles
#define KSEL 10
#define MT 128          // tiles per CTA (k1)
#define NCHK 16         // K chunks of 64

static __device__ float g_scores[NT];
static __device__ float g_outv[NT*32];

#define SWZ(o) ((o) ^ (((o) >> 3) & 0x70))

// float smem offsets (weights region)
#define F_W2  0
#define F_W3  256
#define F_B1  512
#define F_B2  544
#define F_B3  552
#define F_WSC 584
#define F_BSC 616
// byte offsets (stage region)
#define O_STAGE 4096
#define STG_SZ  40960
#define S_AH 0
#define S_AL 16384
#define S_BH 32768
#define S_BL 36864
#define SMEM_K1 (O_STAGE + 2*STG_SZ)   // 86016 B

__device__ __forceinline__ uint32_t s2u(const void* p){
    uint32_t a;
    asm("{ .reg .u64 t; cvta.to.shared.u64 t, %1; cvt.u32.u64 %0, t; }" : "=r"(a) : "l"(p));
    return a;
}
// pack {bf16(x1):bf16(x0)} (x0 in low half)
__device__ __forceinline__ uint32_t bf2pack(float x0, float x1){
    uint32_t r; asm("cvt.rn.bf16x2.f32 %0, %1, %2;" : "=r"(r) : "f"(x1), "f"(x0)); return r;
}
__device__ __forceinline__ void ldsm4(uint32_t a, uint32_t r[4]){
    asm volatile("ldmatrix.sync.aligned.m8n8.x4.shared.b16 {%0,%1,%2,%3}, [%4];"
        : "=r"(r[0]), "=r"(r[1]), "=r"(r[2]), "=r"(r[3]) : "r"(a));
}
__device__ __forceinline__ void mma16816(float c[4], const uint32_t a[4], uint32_t b0, uint32_t b1){
    asm volatile("mma.sync.aligned.m16n8k16.row.col.f32.bf16.bf16.f32 "
        "{%0,%1,%2,%3}, {%4,%5,%6,%7}, {%8,%9}, {%0,%1,%2,%3};"
        : "+f"(c[0]), "+f"(c[1]), "+f"(c[2]), "+f"(c[3])
        : "r"(a[0]), "r"(a[1]), "r"(a[2]), "r"(a[3]), "r"(b0), "r"(b1));
}

// ======= Kernel 1: bf16-split HMMA GEMM (M=128,N=32,K=1024) + fused MLP epilogue ===
__global__ __launch_bounds__(256, 2)
void k1(const float* __restrict__ x,  const float* __restrict__ W1, const float* __restrict__ b1,
        const float* __restrict__ W2, const float* __restrict__ b2,
        const float* __restrict__ W3, const float* __restrict__ b3,
        const float* __restrict__ Wsc, const float* __restrict__ bsc)
{
    extern __shared__ char smem[];
    float* sf = (float*)smem;
    const uint32_t sb = s2u(smem);
    const int tid = threadIdx.x;
    const int wid = tid >> 5;
    const int lid = tid & 31;
    const int t0  = blockIdx.x * MT;

    for (int i = tid; i < 256; i += 256){ sf[F_W2 + i] = W2[i]; sf[F_W3 + i] = W3[i]; }
    if (tid < 32){ sf[F_B1 + tid] = b1[tid]; sf[F_B3 + tid] = b3[tid]; sf[F_WSC + tid] = Wsc[tid]; }
    if (tid < 8) sf[F_B2 + tid] = b2[tid];
    if (tid == 0) sf[F_BSC] = bsc[0];

    float4 ra[8], rb[2];

    auto LD = [&](int c){
        const int k0 = c * 64;
#pragma unroll
        for (int j = 0; j < 8; j++){
            int f = tid + 256*j; int row = f >> 4, qc = f & 15;
            ra[j] = __ldg((const float4*)(x + (size_t)(t0 + row) * Dq + k0) + qc);
        }
#pragma unroll
        for (int j = 0; j < 2; j++){
            int f = tid + 256*j; int row = f >> 4, qc = f & 15;
            rb[j] = __ldg((const float4*)(W1 + (size_t)row * Dq + k0) + qc);
        }
    };
    auto ST = [&](int buf){
        const uint32_t stg = O_STAGE + buf * STG_SZ;
#pragma unroll
        for (int j = 0; j < 8; j++){
            int f = tid + 256*j; int row = f >> 4, qc = f & 15;
            float4 v = ra[j];
            uint32_t h0 = bf2pack(v.x, v.y), h1 = bf2pack(v.z, v.w);
            float hx = __uint_as_float(h0 << 16), hy = __uint_as_float(h0 & 0xffff0000u);
            float hz = __uint_as_float(h1 << 16), hw = __uint_as_float(h1 & 0xffff0000u);
            uint32_t l0 = bf2pack(v.x - hx, v.y - hy), l1 = bf2pack(v.z - hz, v.w - hw);
            uint32_t bo = SWZ((uint32_t)(row * 128 + qc * 8));
            *(uint2*)(smem + stg + S_AH + bo) = make_uint2(h0, h1);
            *(uint2*)(smem + stg + S_AL + bo) = make_uint2(l0, l1);
        }
#pragma unroll
        for (int j = 0; j < 2; j++){
            int f = tid + 256*j; int row = f >> 4, qc = f & 15;
            float4 v = rb[j];
            uint32_t h0 = bf2pack(v.x, v.y), h1 = bf2pack(v.z, v.w);
            float hx = __uint_as_float(h0 << 16), hy = __uint_as_float(h0 & 0xffff0000u);
            float hz = __uint_as_float(h1 << 16), hw = __uint_as_float(h1 & 0xffff0000u);
            uint32_t l0 = bf2pack(v.x - hx, v.y - hy), l1 = bf2pack(v.z - hz, v.w - hw);
            uint32_t bo = SWZ((uint32_t)(row * 128 + qc * 8));
            *(uint2*)(smem + stg + S_BH + bo) = make_uint2(h0, h1);
            *(uint2*)(smem + stg + S_BL + bo) = make_uint2(l0, l1);
        }
    };

    LD(0);
    ST(0);
    __syncthreads();

    float acc[4][4];
#pragma unroll
    for (int i = 0; i < 4; i++)
#pragma unroll
        for (int j = 0; j < 4; j++) acc[i][j] = 0.f;

    const int arow = wid * 16 + (lid & 15);
    const int bn   = (lid & 7) + ((lid >> 4) * 8);

    for (int c = 0; c < NCHK; c++){
        if (c + 1 < NCHK) LD(c + 1);
        const uint32_t stg = O_STAGE + (c & 1) * STG_SZ;
#pragma unroll
        for (int k = 0; k < 4; k++){
            uint32_t ah[4], al[4];
            uint32_t ab = SWZ((uint32_t)(arow * 128 + k * 32 + ((lid >> 4) * 16)));
            ldsm4(sb + stg + S_AH + ab, ah);
            ldsm4(sb + stg + S_AL + ab, al);
            const uint32_t kb = (uint32_t)(k * 32 + ((lid >> 3) & 1) * 16);
#pragma unroll
            for (int nb2 = 0; nb2 < 2; nb2++){
                uint32_t bh[4], bl[4];
                uint32_t bb = SWZ((uint32_t)((nb2 * 16 + bn) * 128) + kb);
                ldsm4(sb + stg + S_BH + bb, bh);
                ldsm4(sb + stg + S_BL + bb, bl);
                mma16816(acc[nb2*2],   ah, bh[0], bh[1]);
                mma16816(acc[nb2*2+1], ah, bh[2], bh[3]);
                mma16816(acc[nb2*2],   ah, bl[0], bl[1]);
                mma16816(acc[nb2*2+1], ah, bl[2], bl[3]);
                mma16816(acc[nb2*2],   al, bh[0], bh[1]);
                mma16816(acc[nb2*2+1], al, bh[2], bh[3]);
            }
        }
        if (c + 1 < NCHK){
            ST((c + 1) & 1);
            __syncthreads();
        }
    }

    float* h1s = (float*)(smem + O_STAGE);
    {
        const int gid = lid >> 2, qd = lid & 3;
        const int r0 = wid * 16 + gid, r1 = r0 + 8;
#pragma unroll
        for (int nsub = 0; nsub < 4; nsub++){
            h1s[r0*33 + nsub*8 + qd*2 + 0] = acc[nsub][0];
            h1s[r0*33 + nsub*8 + qd*2 + 1] = acc[nsub][1];
            h1s[r1*33 + nsub*8 + qd*2 + 0] = acc[nsub][2];
            h1s[r1*33 + nsub*8 + qd*2 + 1] = acc[nsub][3];
        }
    }
    __syncthreads();

    if (tid < MT){
        const int m = tid;
        const size_t t = (size_t)t0 + m;
        float hv[32];
#pragma unroll
        for (int h = 0; h < 32; h++){
            float v = h1s[m*33 + h] + sf[F_B1 + h];
            hv[h] = v > 0.f ? v : 0.f;
        }
        float h2[8];
#pragma unroll
        for (int g = 0; g < 8; g++){
            float s = sf[F_B2 + g];
#pragma unroll
            for (int h = 0; h < 32; h++) s = fmaf(sf[F_W2 + g*32 + h], hv[h], s);
            h2[g] = s > 0.f ? s : 0.f;
        }
        float sc = sf[F_BSC];
#pragma unroll
        for (int h4 = 0; h4 < 8; h4++){
            float4 o4; float* op = &o4.x;
#pragma unroll
            for (int kk = 0; kk < 4; kk++){
                const int h = h4*4 + kk;
                float s = sf[F_B3 + h];
#pragma unroll
                for (int g = 0; g < 8; g++) s = fmaf(sf[F_W3 + h*8 + g], h2[g], s);
                s = s > 0.f ? s : 0.f;
                op[kk] = s;
                sc = fmaf(sf[F_WSC + h], s, sc);
            }
            *(float4*)(&g_outv[t*32 + h4*4]) = o4;
        }
        g_scores[t] = sc > 0.f ? sc : 0.f;
    }
}

// ======= Kernel 2: stable top/bottom-k select + classifier ========================
// Register-resident sorted lists + unrolled compare-swap insertion; selection via
// 10-round multi-way pointer merge (heads in registers, block shfl-tree reduce).
// Key = (score_bits << 32) | index == jnp.argsort stable (score, index) order.
#define K2T 512
__global__ __launch_bounds__(K2T) void k2(
    const float* __restrict__ Wc1, const float* __restrict__ bc1,
    const float* __restrict__ Wc2, const float* __restrict__ bc2,
    const float* __restrict__ Wc3, const float* __restrict__ bc3,
    float* __restrict__ outp)
{
    const int b = blockIdx.x, tid = threadIdx.x;
    const int lane = tid & 31, warp = tid >> 5;   // 16 warps
    __shared__ unsigned long long wred[16], swin;
    __shared__ unsigned long long selkey[20];
    __shared__ float feat[692], z1[32], z2[32];

    // bot: ascending (bot[0] = min). top: DESCENDING (top[0] = max).
    unsigned long long bot[KSEL], top[KSEL];
#pragma unroll
    for (int j = 0; j < KSEL; j++){ bot[j] = ~0ull; top[j] = 0ull; }

    const float4* sp = (const float4*)(g_scores + (size_t)b * Nq);
    for (int v = tid; v < Nq/4; v += K2T){
        float4 s4 = sp[v];
        float ss[4] = {s4.x, s4.y, s4.z, s4.w};
#pragma unroll
        for (int e = 0; e < 4; e++){
            unsigned long long key = ((unsigned long long)__float_as_uint(ss[e]) << 32) | (unsigned)(v*4 + e);
            if (key < bot[KSEL-1]){
                bot[KSEL-1] = key;
#pragma unroll
                for (int j = KSEL-1; j > 0; j--){
                    unsigned long long a0 = bot[j-1], a1 = bot[j];
                    bot[j-1] = a0 < a1 ? a0 : a1;
                    bot[j]   = a0 < a1 ? a1 : a0;
                }
            }
            if (key > top[KSEL-1]){
                top[KSEL-1] = key;
#pragma unroll
                for (int j = KSEL-1; j > 0; j--){
                    unsigned long long a0 = top[j-1], a1 = top[j];
                    top[j-1] = a0 > a1 ? a0 : a1;
                    top[j]   = a0 > a1 ? a1 : a0;
                }
            }
        }
    }
    __syncthreads();

    // ---- 10-round min-merge (bottom-10, ascending into selkey[0..9]) ----
    for (int i = 0; i < KSEL; i++){
        unsigned long long v = bot[0];
#pragma unroll
        for (int o = 16; o > 0; o >>= 1){
            unsigned long long u = __shfl_down_sync(0xffffffffu, v, o);
            if (u < v) v = u;
        }
        if (lane == 0) wred[warp] = v;
        __syncthreads();
        if (warp == 0){
            unsigned long long w = (lane < 16) ? wred[lane] : ~0ull;
#pragma unroll
            for (int o = 8; o > 0; o >>= 1){
                unsigned long long u = __shfl_down_sync(0xffffffffu, w, o);
                if (u < w) w = u;
            }
            if (lane == 0){ swin = w; selkey[i] = w; }
        }
        __syncthreads();
        if (bot[0] == swin){   // unique keys -> exactly one winner
#pragma unroll
            for (int j = 0; j < KSEL-1; j++) bot[j] = bot[j+1];
            bot[KSEL-1] = ~0ull;
        }
        __syncthreads();
    }
    // ---- 10-round max-merge (top-10; round i = i-th largest -> selkey[19-i]) ----
    for (int i = 0; i < KSEL; i++){
        unsigned long long v = top[0];
#pragma unroll
        for (int o = 16; o > 0; o >>= 1){
            unsigned long long u = __shfl_down_sync(0xffffffffu, v, o);
            if (u > v) v = u;
        }
        if (lane == 0) wred[warp] = v;
        __syncthreads();
        if (warp == 0){
            unsigned long long w = (lane < 16) ? wred[lane] : 0ull;
#pragma unroll
            for (int o = 8; o > 0; o >>= 1){
                unsigned long long u = __shfl_down_sync(0xffffffffu, w, o);
                if (u > w) w = u;
            }
            if (lane == 0){ swin = w; selkey[19-i] = w; }
        }
        __syncthreads();
        if (top[0] == swin){
#pragma unroll
            for (int j = 0; j < KSEL-1; j++) top[j] = top[j+1];
            top[KSEL-1] = 0ull;
        }
        __syncthreads();
    }

    // features: [g_sc(0..19) | avg(20..51) | g_flat(52..691): 52 + h*20 + j]
    for (int i = tid; i < 640; i += K2T){
        int j = i >> 5, h = i & 31;
        int n = (int)(selkey[j] & 0xFFFFFFFFull);
        feat[52 + h*20 + j] = g_outv[((size_t)b*Nq + n)*32 + h];
    }
    if (tid < 20) feat[tid] = __uint_as_float((unsigned)(selkey[tid] >> 32));
    __syncthreads();
    if (tid < 32){
        float s = 0.f;
#pragma unroll
        for (int j = 0; j < 20; j++) s += feat[52 + tid*20 + j];
        feat[20 + tid] = s * (1.f/20.f);
    }
    __syncthreads();

    // classifier layer 1: 8 threads per output + shfl reduce (threads 0..255)
    if (tid < 256){
        int o = tid >> 3, p = tid & 7;
        const float* wr = Wc1 + (size_t)o * 692;
        float s = 0.f;
        for (int i = p; i < 692; i += 8) s = fmaf(wr[i], feat[i], s);
        s += __shfl_xor_sync(0xffffffffu, s, 1);
        s += __shfl_xor_sync(0xffffffffu, s, 2);
        s += __shfl_xor_sync(0xffffffffu, s, 4);
        if (p == 0){ s += bc1[o]; z1[o] = s > 0.f ? s : 0.f; }
    }
    __syncthreads();
    if (tid < 32){
        float s = bc2[tid];
#pragma unroll
        for (int i = 0; i < 32; i++) s = fmaf(Wc2[tid*32+i], z1[i], s);
        z2[tid] = s > 0.f ? s : 0.f;
    }
    __syncthreads();
    if (tid == 0){
        float s = bc3[0];
#pragma unroll
        for (int i = 0; i < 32; i++) s = fmaf(Wc3[i], z2[i], s);
        outp[b] = 1.f / (1.f + expf(-s));
    }
}

extern "C" void kernel_launch(void* const* d_in, const int* in_sizes, int n_in,
                              void* d_out, int out_size) {
    const float* x   = (const float*)d_in[0];
    const float* W1  = (const float*)d_in[1];
    const float* b1  = (const float*)d_in[2];
    const float* W2  = (const float*)d_in[3];
    const float* b2  = (const float*)d_in[4];
    const float* W3  = (const float*)d_in[5];
    const float* b3  = (const float*)d_in[6];
    const float* Wsc = (const float*)d_in[7];
    const float* bsc = (const float*)d_in[8];
    const float* Wc1 = (const float*)d_in[9];
    const float* bc1 = (const float*)d_in[10];
    const float* Wc2 = (const float*)d_in[11];
    const float* bc2 = (const float*)d_in[12];
    const float* Wc3 = (const float*)d_in[13];
    const float* bc3 = (const float*)d_in[14];
    float* outp = (float*)d_out;

    cudaFuncSetAttribute(k1, cudaFuncAttributeMaxDynamicSharedMemorySize, SMEM_K1);
    k1<<<NT/MT, 256, SMEM_K1>>>(x, W1, b1, W2, b2, W3, b3, Wsc, bsc);
    k2<<<Bq, K2T>>>(Wc1, bc1, Wc2, bc2, Wc3, bc3, outp);
}